// round 3
// baseline (speedup 1.0000x reference)
#include <cuda_runtime.h>
#include <cuda_bf16.h>
#include <math.h>

// Problem constants
#define BATCH 64
#define SEQ   512
#define HID   512
#define EMB   512
#define GATES 2048              // 4*HID
#define MROWS (SEQ*BATCH)       // 32768
#define HB    (BATCH*HID)       // one (dir) h plane
#define NBLK  128               // persistent grid size

// ---------------------------------------------------------------------------
// Scratch (static __device__ globals; no runtime allocation)
// ---------------------------------------------------------------------------
__device__ float g_xe  [SEQ*BATCH*HID];     // [s][b][h]
__device__ float g_xp_f[SEQ*BATCH*GATES];   // [s][b][gk]  (gk = g*512 + k)
__device__ float g_xp_b[SEQ*BATCH*GATES];
__device__ float g_hs_f[SEQ*BATCH*HID];     // [t][b][k]  (processing order)
__device__ float g_hs_b[SEQ*BATCH*HID];
__device__ float g_h   [2*2*BATCH*HID];     // [buf][dir][b][k]

__device__ unsigned g_bar_cnt = 0;
__device__ unsigned g_bar_gen = 0;

// ---------------------------------------------------------------------------
// Software grid barrier (all NBLK blocks co-resident: 1 block/SM, 128 <= 148)
// ---------------------------------------------------------------------------
__device__ __forceinline__ void grid_bar(unsigned nb)
{
    __syncthreads();
    if (threadIdx.x == 0) {
        __threadfence();
        unsigned gen = *(volatile unsigned*)&g_bar_gen;
        if (atomicAdd(&g_bar_cnt, 1u) == nb - 1u) {
            g_bar_cnt = 0;              // reset BEFORE release
            __threadfence();
            atomicAdd(&g_bar_gen, 1u);  // release
        } else {
            while (*(volatile unsigned*)&g_bar_gen == gen)
                __nanosleep(64);
        }
        __threadfence();
    }
    __syncthreads();
}

// ---------------------------------------------------------------------------
// Embedding gather: xe[s][b][:] = emb[x[b][s]][:]
// ---------------------------------------------------------------------------
__global__ void embed_kernel(const int* __restrict__ x, const float* __restrict__ emb)
{
    int row = blockIdx.x;              // s*64 + b
    int s = row >> 6;
    int b = row & 63;
    int idx = x[b*SEQ + s];
    const float4* src = (const float4*)(emb + (long long)idx*EMB);
    float4* dst = (float4*)(g_xe + row*HID);
    dst[threadIdx.x] = src[threadIdx.x];   // 128 threads * float4
}

// ---------------------------------------------------------------------------
// Input-projection GEMM, both directions via blockIdx.z.
// C[m][n] = sum_h A[m][h]*W[n][h] + bx[n] + bh[n]
// M=32768, N=2048, K=512. BM=BN=128, BK=16, 256 thr, 8x8 microtile.
// ---------------------------------------------------------------------------
__global__ void gemm_xproj(int selA,
                           const float* __restrict__ WF, const float* __restrict__ bxF,
                           const float* __restrict__ bhF,
                           const float* __restrict__ WB, const float* __restrict__ bxB,
                           const float* __restrict__ bhB)
{
    int d = blockIdx.z;
    const float* A = (selA == 0) ? g_xe : (d == 0 ? g_hs_f : g_hs_b);
    const float* W  = d ? WB  : WF;
    const float* b1 = d ? bxB : bxF;
    const float* b2 = d ? bhB : bhF;
    float* C = d ? g_xp_b : g_xp_f;

    __shared__ __align__(16) float As[16][128];
    __shared__ __align__(16) float Bs[16][128];

    int tid = threadIdx.x;
    int m0 = blockIdx.y * 128;
    int n0 = blockIdx.x * 128;
    int tx = tid & 15;
    int ty = tid >> 4;

    float acc[8][8];
    #pragma unroll
    for (int i = 0; i < 8; i++)
        #pragma unroll
        for (int j = 0; j < 8; j++) acc[i][j] = 0.f;

    for (int kt = 0; kt < HID/16; kt++) {
        int k0 = kt * 16;
        #pragma unroll
        for (int i = 0; i < 2; i++) {
            int e = tid + i*256;
            int row = e >> 2, q = e & 3;
            float4 v = *(const float4*)(A + (m0+row)*HID + k0 + q*4);
            As[q*4+0][row] = v.x; As[q*4+1][row] = v.y;
            As[q*4+2][row] = v.z; As[q*4+3][row] = v.w;
        }
        #pragma unroll
        for (int i = 0; i < 2; i++) {
            int e = tid + i*256;
            int row = e >> 2, q = e & 3;
            float4 v = *(const float4*)(W + (n0+row)*HID + k0 + q*4);
            Bs[q*4+0][row] = v.x; Bs[q*4+1][row] = v.y;
            Bs[q*4+2][row] = v.z; Bs[q*4+3][row] = v.w;
        }
        __syncthreads();
        #pragma unroll
        for (int kk = 0; kk < 16; kk++) {
            float a[8], b[8];
            *(float4*)&a[0] = *(const float4*)&As[kk][ty*8];
            *(float4*)&a[4] = *(const float4*)&As[kk][ty*8+4];
            *(float4*)&b[0] = *(const float4*)&Bs[kk][tx*8];
            *(float4*)&b[4] = *(const float4*)&Bs[kk][tx*8+4];
            #pragma unroll
            for (int i = 0; i < 8; i++)
                #pragma unroll
                for (int j = 0; j < 8; j++)
                    acc[i][j] += a[i]*b[j];
        }
        __syncthreads();
    }
    #pragma unroll
    for (int i = 0; i < 8; i++) {
        int m = m0 + ty*8 + i;
        #pragma unroll
        for (int j = 0; j < 8; j++) {
            int n = n0 + tx*8 + j;
            C[m*GATES + n] = acc[i][j] + b1[n] + b2[n];
        }
    }
}

// ---------------------------------------------------------------------------
// Persistent LSTM layer: both directions, all 512 timesteps, one launch.
// 128 blocks: dir = blk>>6, kc = blk&63 (8 hidden cols, all 4 gates).
// Wh slice (transposed) resident in smem for the whole layer.
// c state in registers (cell->thread mapping static across t).
// Dynamic smem: sW[512][36] + sA[2][16][64] + sG[2][32][64] = 96 KB.
// ---------------------------------------------------------------------------
#define SW_PITCH 36
#define SMEM_LSTM ((512*SW_PITCH + 2*16*64 + 2*32*64) * 4)

__global__ void __launch_bounds__(256, 1)
lstm_layer(const float* __restrict__ WhF, const float* __restrict__ WhB,
           int rev_b, int store_hs)
{
    extern __shared__ float sm[];
    float* sW = sm;                        // [512][36]  (k-major, gkl minor)
    float* sA = sm + 512*SW_PITCH;         // [2][16][64]
    float* sG = sA + 2*16*64;              // [2][32][64]

    const int dir = blockIdx.x >> 6;
    const int kc  = blockIdx.x & 63;
    const int tid = threadIdx.x;
    const int half = tid >> 7;
    const int tid2 = tid & 127;
    const int tx = tid2 & 7;               // gkl micro (4)
    const int ty = tid2 >> 3;              // b micro (4)
    const unsigned nb = gridDim.x;

    const float* Wh  = dir ? WhB : WhF;
    const float* xpb = dir ? g_xp_b : g_xp_f;
    float*       hs  = dir ? g_hs_b : g_hs_f;

    // Load Wh slice transposed: sW[k][gkl], gkl = g*8+j, Wh row = g*512 + kc*8 + j
    for (int e = tid; e < 32*512; e += 256) {
        int gkl = e >> 9;
        int k   = e & 511;
        int g = gkl >> 3, j = gkl & 7;
        sW[k*SW_PITCH + gkl] = Wh[((g*512) + kc*8 + j)*HID + k];
    }
    // Clear owned h slices (both buffers)
    for (int e = tid; e < 2*64*8; e += 256) {
        int buf = e >> 9;
        int r = e & 511;
        int b = r >> 3, j = r & 7;
        g_h[buf*(2*HB) + dir*HB + b*HID + kc*8 + j] = 0.f;
    }
    float creg[2] = {0.f, 0.f};
    grid_bar(nb);

    for (int t = 0; t < SEQ; t++) {
        int xrow = dir ? (rev_b ? (SEQ-1-t) : t) : t;
        const float* xp  = xpb + (long long)xrow * (BATCH*GATES);
        const float* hin = g_h + (t & 1)*(2*HB) + dir*HB;
        float*       hout= g_h + ((t+1) & 1)*(2*HB) + dir*HB;

        float acc[4][4];
        #pragma unroll
        for (int i = 0; i < 4; i++)
            #pragma unroll
            for (int j = 0; j < 4; j++) acc[i][j] = 0.f;

        const int hbase = half * 256;
        for (int ct = 0; ct < 16; ct++) {
            int h0 = hbase + ct*16;
            // stage h tile for this half: 64b x 16k
            #pragma unroll
            for (int i = 0; i < 2; i++) {
                int e = tid2 + i*128;
                int b = e >> 2, q = e & 3;
                float4 v = *(const float4*)(hin + b*HID + h0 + q*4);
                sA[(half*16 + q*4+0)*64 + b] = v.x;
                sA[(half*16 + q*4+1)*64 + b] = v.y;
                sA[(half*16 + q*4+2)*64 + b] = v.z;
                sA[(half*16 + q*4+3)*64 + b] = v.w;
            }
            __syncthreads();
            #pragma unroll
            for (int kk = 0; kk < 16; kk++) {
                float4 a4 = *(const float4*)&sA[(half*16 + kk)*64 + ty*4];
                float4 b4 = *(const float4*)&sW[(h0 + kk)*SW_PITCH + tx*4];
                float a[4] = {a4.x, a4.y, a4.z, a4.w};
                float b[4] = {b4.x, b4.y, b4.z, b4.w};
                #pragma unroll
                for (int i = 0; i < 4; i++)
                    #pragma unroll
                    for (int j = 0; j < 4; j++)
                        acc[i][j] += a[i]*b[j];
            }
            __syncthreads();
        }

        // partial gate sums -> smem
        #pragma unroll
        for (int j = 0; j < 4; j++)
            #pragma unroll
            for (int i = 0; i < 4; i++)
                sG[(half*32 + tx*4 + j)*64 + ty*4 + i] = acc[i][j];
        __syncthreads();

        // pointwise: 512 cells, 2 per thread (mapping static across t -> c in regs)
        #pragma unroll
        for (int r = 0; r < 2; r++) {
            int cell = tid + r*256;
            int j = cell >> 6;
            int b = cell & 63;
            int kg = kc*8 + j;

            float fv = sG[( 0 + j)*64 + b] + sG[(32 +  0 + j)*64 + b] + xp[b*GATES +       kg];
            float iv = sG[( 8 + j)*64 + b] + sG[(32 +  8 + j)*64 + b] + xp[b*GATES +  512 + kg];
            float gv = sG[(16 + j)*64 + b] + sG[(32 + 16 + j)*64 + b] + xp[b*GATES + 1024 + kg];
            float ov = sG[(24 + j)*64 + b] + sG[(32 + 24 + j)*64 + b] + xp[b*GATES + 1536 + kg];

            float f  = 1.f/(1.f + expf(-fv));
            float ii = 1.f/(1.f + expf(-iv));
            float gg = tanhf(gv);
            float o  = 1.f/(1.f + expf(-ov));

            float c = f*creg[r] + ii*gg;
            creg[r] = c;
            float h = o*tanhf(c);
            hout[b*HID + kg] = h;
            if (store_hs) hs[(long long)t*HB + b*HID + kg] = h;
        }
        grid_bar(nb);
    }
}

// ---------------------------------------------------------------------------
// Final FC + sigmoid: out[b] = sigmoid(h_f . w[0:512] + h_b . w[512:1024] + b)
// Final states live in g_h buffer 0 (t=511 wrote buf (511+1)&1 == 0).
// ---------------------------------------------------------------------------
__global__ void final_fc(const float* __restrict__ fcw, const float* __restrict__ fcb,
                         float* __restrict__ out)
{
    int b = blockIdx.x;
    const float* hf = g_h + 0*HB + b*HID;
    const float* hb = g_h + 1*HB + b*HID;
    float s = 0.f;
    for (int k = threadIdx.x; k < HID; k += 128)
        s += hf[k]*fcw[k] + hb[k]*fcw[HID + k];
    #pragma unroll
    for (int off = 16; off > 0; off >>= 1)
        s += __shfl_xor_sync(0xFFFFFFFFu, s, off);
    __shared__ float red[4];
    int warp = threadIdx.x >> 5, lane = threadIdx.x & 31;
    if (lane == 0) red[warp] = s;
    __syncthreads();
    if (threadIdx.x == 0) {
        float tot = red[0] + red[1] + red[2] + red[3] + fcb[0];
        out[b] = 1.f/(1.f + expf(-tot));
    }
}

// ---------------------------------------------------------------------------
// Launch sequence: 6 graph nodes total.
// ---------------------------------------------------------------------------
extern "C" void kernel_launch(void* const* d_in, const int* in_sizes, int n_in,
                              void* d_out, int out_size)
{
    const int*   x    = (const int*)  d_in[0];
    const float* emb  = (const float*)d_in[1];
    const float* Wx_f = (const float*)d_in[2];
    const float* bx_f = (const float*)d_in[3];
    const float* Wh_f = (const float*)d_in[4];
    const float* bh_f = (const float*)d_in[5];
    const float* Wx_b = (const float*)d_in[6];
    const float* bx_b = (const float*)d_in[7];
    const float* Wh_b = (const float*)d_in[8];
    const float* bh_b = (const float*)d_in[9];
    const float* fcw  = (const float*)d_in[10];
    const float* fcb  = (const float*)d_in[11];
    float* out = (float*)d_out;

    const int WL = 4*HID*HID;   // per-layer weight stride
    const int BL = 4*HID;       // per-layer bias stride

    cudaFuncSetAttribute(lstm_layer, cudaFuncAttributeMaxDynamicSharedMemorySize, SMEM_LSTM);

    dim3 ggrid(GATES/128, MROWS/128, 2);   // (16, 256, 2)

    // 1. embedding
    embed_kernel<<<MROWS, 128>>>(x, emb);

    // 2. layer-0 input projections (A = xe), bias = bx + bh
    gemm_xproj<<<ggrid, 256>>>(0, Wx_f, bx_f, bh_f, Wx_b, bx_b, bh_b);

    // 3. layer-0 recurrence (backward reads xp row 511-t, store hs)
    lstm_layer<<<NBLK, 256, SMEM_LSTM>>>(Wh_f, Wh_b, 1, 1);

    // 4. layer-1 input projections (A = hs per dir)
    gemm_xproj<<<ggrid, 256>>>(1, Wx_f + WL, bx_f + BL, bh_f + BL,
                                  Wx_b + WL, bx_b + BL, bh_b + BL);

    // 5. layer-1 recurrence (both dirs read xp row t)
    lstm_layer<<<NBLK, 256, SMEM_LSTM>>>(Wh_f + WL, Wh_b + WL, 0, 0);

    // 6. final FC + sigmoid
    final_fc<<<BATCH, 128>>>(fcw, fcb, out);
}

// round 4
// speedup vs baseline: 2.4163x; 2.4163x over previous
#include <cuda_runtime.h>
#include <math.h>
#include <stdint.h>

// Problem constants
#define BATCH 64
#define SEQ   512
#define HID   512
#define GATES 2048              // 4*HID
#define MROWS (SEQ*BATCH)       // 32768
#define HB    (BATCH*HID)       // one (dir) h plane
#define NBLK  128               // persistent grid size

// ---------------------------------------------------------------------------
// Scratch (static __device__ globals; no runtime allocation)
// ---------------------------------------------------------------------------
__device__ float g_xe  [MROWS*HID];                  // [s*64+b][h]
__device__ float g_xp_f[(size_t)SEQ*GATES*BATCH];    // [s][gk][b]  (transposed!)
__device__ float g_xp_b[(size_t)SEQ*GATES*BATCH];
__device__ float g_hs_f[MROWS*HID];                  // [t*64+b][k]
__device__ float g_hs_b[MROWS*HID];
__device__ float g_h   [2*2*HB];                     // [buf][dir][b][k]

__device__ unsigned g_bar_cnt = 0;
__device__ unsigned g_bar_gen = 0;

// ---------------------------------------------------------------------------
// tf32 helpers
// ---------------------------------------------------------------------------
__device__ __forceinline__ uint32_t f2tf(float x)
{
    uint32_t r;
    asm("cvt.rna.tf32.f32 %0, %1;" : "=r"(r) : "f"(x));
    return r;
}

// D = A(16x8) * B(8x8) + D, tf32 inputs, fp32 accum.
__device__ __forceinline__ void mma8(float* c, const uint32_t* a, uint32_t b0, uint32_t b1)
{
    asm volatile(
        "mma.sync.aligned.m16n8k8.row.col.f32.tf32.tf32.f32 "
        "{%0,%1,%2,%3},{%4,%5,%6,%7},{%8,%9},{%0,%1,%2,%3};"
        : "+f"(c[0]), "+f"(c[1]), "+f"(c[2]), "+f"(c[3])
        : "r"(a[0]), "r"(a[1]), "r"(a[2]), "r"(a[3]), "r"(b0), "r"(b1));
}

// ---------------------------------------------------------------------------
// Software grid barrier (all NBLK blocks co-resident: 1 block/SM)
// ---------------------------------------------------------------------------
__device__ __forceinline__ void grid_bar(unsigned nb)
{
    __syncthreads();
    if (threadIdx.x == 0) {
        __threadfence();
        unsigned gen = *(volatile unsigned*)&g_bar_gen;
        if (atomicAdd(&g_bar_cnt, 1u) == nb - 1u) {
            g_bar_cnt = 0;
            __threadfence();
            atomicAdd(&g_bar_gen, 1u);
        } else {
            while (*(volatile unsigned*)&g_bar_gen == gen)
                __nanosleep(64);
        }
        __threadfence();
    }
    __syncthreads();
}

// ---------------------------------------------------------------------------
// Embedding gather: xe[s*64+b][:] = emb[x[b][s]][:]
// ---------------------------------------------------------------------------
__global__ void embed_kernel(const int* __restrict__ x, const float* __restrict__ emb)
{
    int row = blockIdx.x;              // s*64 + b
    int s = row >> 6;
    int b = row & 63;
    int idx = x[b*SEQ + s];
    const float4* src = (const float4*)(emb + (size_t)idx*HID);
    float4* dst = (float4*)(g_xe + (size_t)row*HID);
    dst[threadIdx.x] = src[threadIdx.x];
}

// ---------------------------------------------------------------------------
// Input-projection GEMM (tf32 tensor cores), both directions via blockIdx.z.
// C_T[s][n][b] = sum_h A[s*64+b][h]*W[n][h] + bx[n] + bh[n]
// M=32768, N=2048, K=512. BM=128, BN=64, BK=32. 8 warps = 4(m) x 2(n).
// smem tiles pair-permuted so each MMA fragment is a single lds.64:
//   s*[kt][row][2t+c] = X[row][kt*8 + t + 4c]
// ---------------------------------------------------------------------------
#define KTP_A 1028   // words per kt slab of sA (128*8 + 4 pad)
#define KTP_B 516    // words per kt slab of sB (64*8 + 4 pad)

__global__ void __launch_bounds__(256)
gemm_xproj(int selA,
           const float* __restrict__ WF, const float* __restrict__ bxF,
           const float* __restrict__ bhF,
           const float* __restrict__ WB, const float* __restrict__ bxB,
           const float* __restrict__ bhB)
{
    __shared__ uint32_t sA[4*KTP_A];
    __shared__ uint32_t sB[4*KTP_B];

    int d = blockIdx.z;
    const float* A  = (selA == 0) ? g_xe : (d ? g_hs_b : g_hs_f);
    const float* W  = d ? WB  : WF;
    const float* b1 = d ? bxB : bxF;
    const float* b2 = d ? bhB : bhF;
    float* C = d ? g_xp_b : g_xp_f;

    int m0 = blockIdx.y * 128;
    int n0 = blockIdx.x * 64;
    int tid = threadIdx.x;
    int wid = tid >> 5, lane = tid & 31;
    int g = lane >> 2, tq = lane & 3;
    int wm = wid >> 1, wn = wid & 1;

    float acc[2][4][4];
    #pragma unroll
    for (int mt = 0; mt < 2; mt++)
        #pragma unroll
        for (int nt = 0; nt < 4; nt++)
            #pragma unroll
            for (int q = 0; q < 4; q++) acc[mt][nt][q] = 0.f;

    for (int k0 = 0; k0 < HID; k0 += 32) {
        // stage A: 512 octets (kt 0..3, row 0..127), 2 per thread
        #pragma unroll
        for (int i = 0; i < 2; i++) {
            int o = tid + i*256;
            int kt = o & 3, row = o >> 2;
            const float* src = A + (size_t)(m0+row)*HID + k0 + kt*8;
            float4 v1 = *(const float4*)src;
            float4 v2 = *(const float4*)(src + 4);
            uint2* dst = (uint2*)(sA + kt*KTP_A + row*8);
            dst[0] = make_uint2(f2tf(v1.x), f2tf(v2.x));
            dst[1] = make_uint2(f2tf(v1.y), f2tf(v2.y));
            dst[2] = make_uint2(f2tf(v1.z), f2tf(v2.z));
            dst[3] = make_uint2(f2tf(v1.w), f2tf(v2.w));
        }
        // stage B: 256 octets (kt 0..3, row 0..63), 1 per thread
        {
            int kt = tid & 3, row = tid >> 2;
            const float* src = W + (size_t)(n0+row)*HID + k0 + kt*8;
            float4 v1 = *(const float4*)src;
            float4 v2 = *(const float4*)(src + 4);
            uint2* dst = (uint2*)(sB + kt*KTP_B + row*8);
            dst[0] = make_uint2(f2tf(v1.x), f2tf(v2.x));
            dst[1] = make_uint2(f2tf(v1.y), f2tf(v2.y));
            dst[2] = make_uint2(f2tf(v1.z), f2tf(v2.z));
            dst[3] = make_uint2(f2tf(v1.w), f2tf(v2.w));
        }
        __syncthreads();

        #pragma unroll
        for (int kt = 0; kt < 4; kt++) {
            uint32_t a[2][4];
            #pragma unroll
            for (int mt = 0; mt < 2; mt++) {
                int r0 = wm*32 + mt*16 + g;
                uint2 lo = *(const uint2*)(sA + kt*KTP_A + r0*8 + 2*tq);
                uint2 hi = *(const uint2*)(sA + kt*KTP_A + (r0+8)*8 + 2*tq);
                a[mt][0] = lo.x; a[mt][1] = hi.x; a[mt][2] = lo.y; a[mt][3] = hi.y;
            }
            #pragma unroll
            for (int nt = 0; nt < 4; nt++) {
                int r = wn*32 + nt*8 + g;
                uint2 bb = *(const uint2*)(sB + kt*KTP_B + r*8 + 2*tq);
                mma8(acc[0][nt], a[0], bb.x, bb.y);
                mma8(acc[1][nt], a[1], bb.x, bb.y);
            }
        }
        __syncthreads();
    }

    // epilogue: bias + store transposed C[s][n][b]
    #pragma unroll
    for (int mt = 0; mt < 2; mt++) {
        int m = m0 + wm*32 + mt*16 + g;     // rows m, m+8
        int s1 = m >> 6,      bb1 = m & 63;
        int s2 = (m+8) >> 6,  bb2 = (m+8) & 63;
        #pragma unroll
        for (int nt = 0; nt < 4; nt++) {
            int n = n0 + wn*32 + nt*8 + 2*tq;    // cols n, n+1
            float bv0 = b1[n]   + b2[n];
            float bv1 = b1[n+1] + b2[n+1];
            C[((size_t)s1*GATES + n  )*64 + bb1] = acc[mt][nt][0] + bv0;
            C[((size_t)s1*GATES + n+1)*64 + bb1] = acc[mt][nt][1] + bv1;
            C[((size_t)s2*GATES + n  )*64 + bb2] = acc[mt][nt][2] + bv0;
            C[((size_t)s2*GATES + n+1)*64 + bb2] = acc[mt][nt][3] + bv1;
        }
    }
}

// ---------------------------------------------------------------------------
// Persistent LSTM layer (tf32 tensor cores), both directions, all 512 steps.
// 128 blocks: dir = blk>>6, kc = blk&63 -> 32 gate-rows (4 gates x 8 hid cols).
// Warp (mt = wid&1, ks = wid>>1): m-half 16 rows, k-slice 128.
// Weights live in REGISTERS as A fragments (16 frags x 4 = 64 regs/thread).
// Per step: stage h -> smem (tf32, pair-permuted), 128 MMAs/warp,
// 4-way k-partial reduce via smem, fused pointwise (c in registers).
// ---------------------------------------------------------------------------
#define SHP 516    // words per kt slab of sH (64*8 + 4 pad)
#define SGP 68     // padded row pitch of sG
#define SMEM_LSTM ((64*SHP + 4*32*SGP)*4)   // 166912 bytes

__global__ void __launch_bounds__(256, 1)
lstm_layer(const float* __restrict__ WhF, const float* __restrict__ WhB,
           int rev_b, int store_hs)
{
    extern __shared__ uint32_t smu[];
    uint32_t* sH = smu;                     // [kt(64)][b(64)][8] pitch SHP
    float*    sG = (float*)(smu + 64*SHP);  // [ks(4)][lr(32)][SGP]

    const int dir = blockIdx.x >> 6;
    const int kc  = blockIdx.x & 63;
    const int tid = threadIdx.x;
    const int wid = tid >> 5, lane = tid & 31;
    const int g = lane >> 2, tq = lane & 3;
    const int mt = wid & 1, ks = wid >> 1;
    const unsigned nb = gridDim.x;

    const float* Wh  = dir ? WhB : WhF;
    const float* xpb = dir ? g_xp_b : g_xp_f;
    float*       hs  = dir ? g_hs_b : g_hs_f;

    // --- preload weights as tf32 A-fragments (once per layer) ---
    const int lr0 = mt*16 + g;
    const int lr1 = lr0 + 8;
    const float* wr0 = Wh + (size_t)((lr0>>3)*512 + kc*8 + (lr0&7)) * HID;
    const float* wr1 = Wh + (size_t)((lr1>>3)*512 + kc*8 + (lr1&7)) * HID;
    uint32_t aw[16][4];
    #pragma unroll
    for (int kt = 0; kt < 16; kt++) {
        int kb = ks*128 + kt*8 + tq;
        aw[kt][0] = f2tf(wr0[kb]);
        aw[kt][1] = f2tf(wr1[kb]);
        aw[kt][2] = f2tf(wr0[kb+4]);
        aw[kt][3] = f2tf(wr1[kb+4]);
    }

    // clear owned h slices (both buffers)
    for (int e = tid; e < 2*64*8; e += 256) {
        int buf = e >> 9, r = e & 511, b = r >> 3, j = r & 7;
        g_h[buf*(2*HB) + dir*HB + b*HID + kc*8 + j] = 0.f;
    }
    float creg[2] = {0.f, 0.f};
    grid_bar(nb);

    for (int t = 0; t < SEQ; t++) {
        int xrow = dir ? (rev_b ? (SEQ-1-t) : t) : t;
        const float* xp  = xpb + (size_t)xrow * (GATES*64);
        const float* hin = g_h + (t & 1)*(2*HB) + dir*HB;
        float*       hout= g_h + ((t+1) & 1)*(2*HB) + dir*HB;

        // --- stage h (tf32, pair-permuted): 4096 octets, 16 per thread ---
        #pragma unroll
        for (int i = 0; i < 16; i++) {
            int o = tid + i*256;
            int oc = o & 63, b = o >> 6;     // consecutive threads -> consecutive k-octets
            const float* src = hin + b*HID + oc*8;
            float4 v1 = *(const float4*)src;
            float4 v2 = *(const float4*)(src + 4);
            uint2* dst = (uint2*)(sH + oc*SHP + b*8);
            dst[0] = make_uint2(f2tf(v1.x), f2tf(v2.x));
            dst[1] = make_uint2(f2tf(v1.y), f2tf(v2.y));
            dst[2] = make_uint2(f2tf(v1.z), f2tf(v2.z));
            dst[3] = make_uint2(f2tf(v1.w), f2tf(v2.w));
        }
        __syncthreads();

        // --- MMA: (m16 x n64) over warp's k-slice of 128 ---
        float acc[8][4];
        #pragma unroll
        for (int nt = 0; nt < 8; nt++)
            #pragma unroll
            for (int q = 0; q < 4; q++) acc[nt][q] = 0.f;

        #pragma unroll
        for (int kt = 0; kt < 16; kt++) {
            const uint32_t* hrow = sH + (ks*16 + kt)*SHP;
            #pragma unroll
            for (int nt = 0; nt < 8; nt++) {
                uint2 bb = *(const uint2*)(hrow + (nt*8 + g)*8 + 2*tq);
                mma8(acc[nt], aw[kt], bb.x, bb.y);
            }
        }

        // --- write k-partials to sG ---
        #pragma unroll
        for (int nt = 0; nt < 8; nt++) {
            int b = nt*8 + 2*tq;
            *(float2*)(sG + (ks*32 + lr0)*SGP + b) = make_float2(acc[nt][0], acc[nt][1]);
            *(float2*)(sG + (ks*32 + lr1)*SGP + b) = make_float2(acc[nt][2], acc[nt][3]);
        }
        __syncthreads();

        // --- pointwise: 512 cells, 2 per thread (static mapping -> c in regs) ---
        #pragma unroll
        for (int r = 0; r < 2; r++) {
            int cell = tid + r*256;
            int j = cell >> 6, b = cell & 63;
            int kg = kc*8 + j;

            float v[4];
            #pragma unroll
            for (int gate = 0; gate < 4; gate++) {
                float s = xp[(gate*512 + kg)*64 + b];
                #pragma unroll
                for (int k2 = 0; k2 < 4; k2++)
                    s += sG[(k2*32 + gate*8 + j)*SGP + b];
                v[gate] = s;
            }
            float f  = 1.f/(1.f + expf(-v[0]));
            float ii = 1.f/(1.f + expf(-v[1]));
            float gg = tanhf(v[2]);
            float o  = 1.f/(1.f + expf(-v[3]));

            float c = f*creg[r] + ii*gg;
            creg[r] = c;
            float h = o*tanhf(c);
            hout[b*HID + kg] = h;
            if (store_hs) hs[(size_t)t*HB + b*HID + kg] = h;
        }
        grid_bar(nb);
    }
}

// ---------------------------------------------------------------------------
// Final FC + sigmoid. Final states live in g_h buffer 0.
// ---------------------------------------------------------------------------
__global__ void final_fc(const float* __restrict__ fcw, const float* __restrict__ fcb,
                         float* __restrict__ out)
{
    int b = blockIdx.x;
    const float* hf = g_h + 0*HB + b*HID;
    const float* hb = g_h + 1*HB + b*HID;
    float s = 0.f;
    for (int k = threadIdx.x; k < HID; k += 128)
        s += hf[k]*fcw[k] + hb[k]*fcw[HID + k];
    #pragma unroll
    for (int off = 16; off > 0; off >>= 1)
        s += __shfl_xor_sync(0xFFFFFFFFu, s, off);
    __shared__ float red[4];
    int warp = threadIdx.x >> 5, lane = threadIdx.x & 31;
    if (lane == 0) red[warp] = s;
    __syncthreads();
    if (threadIdx.x == 0) {
        float tot = red[0] + red[1] + red[2] + red[3] + fcb[0];
        out[b] = 1.f/(1.f + expf(-tot));
    }
}

// ---------------------------------------------------------------------------
// Launch sequence: 6 graph nodes.
// ---------------------------------------------------------------------------
extern "C" void kernel_launch(void* const* d_in, const int* in_sizes, int n_in,
                              void* d_out, int out_size)
{
    const int*   x    = (const int*)  d_in[0];
    const float* emb  = (const float*)d_in[1];
    const float* Wx_f = (const float*)d_in[2];
    const float* bx_f = (const float*)d_in[3];
    const float* Wh_f = (const float*)d_in[4];
    const float* bh_f = (const float*)d_in[5];
    const float* Wx_b = (const float*)d_in[6];
    const float* bx_b = (const float*)d_in[7];
    const float* Wh_b = (const float*)d_in[8];
    const float* bh_b = (const float*)d_in[9];
    const float* fcw  = (const float*)d_in[10];
    const float* fcb  = (const float*)d_in[11];
    float* out = (float*)d_out;

    const int WL = 4*HID*HID;   // per-layer weight stride
    const int BL = 4*HID;       // per-layer bias stride

    cudaFuncSetAttribute(lstm_layer, cudaFuncAttributeMaxDynamicSharedMemorySize, SMEM_LSTM);

    dim3 ggrid(GATES/64, MROWS/128, 2);   // (32, 256, 2)

    // 1. embedding
    embed_kernel<<<MROWS, 128>>>(x, emb);

    // 2. layer-0 input projections (A = xe), bias = bx + bh
    gemm_xproj<<<ggrid, 256>>>(0, Wx_f, bx_f, bh_f, Wx_b, bx_b, bh_b);

    // 3. layer-0 recurrence (backward reads xp row 511-t, store hs)
    lstm_layer<<<NBLK, 256, SMEM_LSTM>>>(Wh_f, Wh_b, 1, 1);

    // 4. layer-1 input projections (A = hs per dir)
    gemm_xproj<<<ggrid, 256>>>(1, Wx_f + WL, bx_f + BL, bh_f + BL,
                                  Wx_b + WL, bx_b + BL, bh_b + BL);

    // 5. layer-1 recurrence (both dirs read xp row t)
    lstm_layer<<<NBLK, 256, SMEM_LSTM>>>(Wh_f + WL, Wh_b + WL, 0, 0);

    // 6. final FC + sigmoid
    final_fc<<<BATCH, 128>>>(fcw, fcb, out);
}

// round 5
// speedup vs baseline: 3.4853x; 1.4424x over previous
#include <cuda_runtime.h>
#include <math.h>
#include <stdint.h>

// Problem constants
#define BATCH 64
#define SEQ   512
#define HID   512
#define GATES 2048              // 4*HID
#define MROWS (SEQ*BATCH)       // 32768
#define HB    (BATCH*HID)       // one (dir) h plane
#define NBLK  128               // persistent grid size

// ---------------------------------------------------------------------------
// Scratch (static __device__ globals; no runtime allocation)
// bf16 pair-permuted layout: a row of 512 k-values = 32 chunks of 16.
// Each chunk = 8 uint32 words storing bf16x2 pairs in order [p0,p4,p1,p5,p2,p6,p3,p7]
// (p_i = pack(k=2i, k=2i+1) within the chunk). A uint2 read at word 2*tq yields
// exactly the (k=2tq.., k=8+2tq..) halves an m16n8k16 fragment needs.
// ---------------------------------------------------------------------------
__device__ uint32_t g_xeb  [(size_t)SEQ*32*BATCH*8];   // [s][chunk][b][8]
__device__ uint32_t g_hsb_f[(size_t)SEQ*32*BATCH*8];   // [t][chunk][b][8]
__device__ uint32_t g_hsb_b[(size_t)SEQ*32*BATCH*8];
__device__ uint32_t g_hb   [2*2*32*BATCH*8];           // [buf][dir][chunk][b][8]
__device__ float    g_xp_f [(size_t)SEQ*GATES*BATCH];  // [s][gk][b]
__device__ float    g_xp_b [(size_t)SEQ*GATES*BATCH];
__device__ float    g_h    [2*HB];                     // [dir][b][k]  (final step only)

__device__ unsigned g_bar_cnt = 0;
__device__ unsigned g_bar_gen = 0;

// ---------------------------------------------------------------------------
// helpers
// ---------------------------------------------------------------------------
__device__ __forceinline__ uint32_t pk(float lo, float hi)
{
    uint32_t r;
    asm("cvt.rn.bf16x2.f32 %0, %1, %2;" : "=r"(r) : "f"(hi), "f"(lo));
    return r;
}

// D(16x8) += A(16x16) * B(16x8), bf16 inputs, fp32 accum.
__device__ __forceinline__ void mma16(float* c, const uint32_t* a, uint32_t b0, uint32_t b1)
{
    asm volatile(
        "mma.sync.aligned.m16n8k16.row.col.f32.bf16.bf16.f32 "
        "{%0,%1,%2,%3},{%4,%5,%6,%7},{%8,%9},{%0,%1,%2,%3};"
        : "+f"(c[0]), "+f"(c[1]), "+f"(c[2]), "+f"(c[3])
        : "r"(a[0]), "r"(a[1]), "r"(a[2]), "r"(a[3]), "r"(b0), "r"(b1));
}

__device__ __forceinline__ uint2 ldcg_u2(const uint32_t* p)
{
    uint2 v;
    asm volatile("ld.global.cg.v2.u32 {%0,%1}, [%2];"
                 : "=r"(v.x), "=r"(v.y) : "l"(p));
    return v;
}

// ---------------------------------------------------------------------------
// Software grid barrier (all NBLK blocks co-resident: 1 block/SM)
// ---------------------------------------------------------------------------
__device__ __forceinline__ void grid_bar(unsigned nb)
{
    __syncthreads();
    __threadfence();                 // every thread: drain its stores to L2
    if (threadIdx.x == 0) {
        unsigned gen = *(volatile unsigned*)&g_bar_gen;
        if (atomicAdd(&g_bar_cnt, 1u) == nb - 1u) {
            g_bar_cnt = 0;
            __threadfence();
            atomicAdd(&g_bar_gen, 1u);
        } else {
            while (*(volatile unsigned*)&g_bar_gen == gen)
                __nanosleep(64);
        }
        __threadfence();
    }
    __syncthreads();
}

// ---------------------------------------------------------------------------
// Embedding gather -> bf16 pair-permuted xe.
// 256 threads, 8 rows/block: warp = one row, thread c handles chunk c (16 floats).
// ---------------------------------------------------------------------------
__global__ void embed_kernel(const int* __restrict__ x, const float* __restrict__ emb)
{
    int row = blockIdx.x*8 + (threadIdx.x >> 5);    // s*64 + b
    int c   = threadIdx.x & 31;                     // chunk
    int s = row >> 6, b = row & 63;
    int idx = x[b*SEQ + s];
    const float* src = emb + (size_t)idx*HID + c*16;
    float4 v0 = *(const float4*)src;
    float4 v1 = *(const float4*)(src + 4);
    float4 v2 = *(const float4*)(src + 8);
    float4 v3 = *(const float4*)(src + 12);
    uint32_t p0 = pk(v0.x,v0.y), p1 = pk(v0.z,v0.w);
    uint32_t p2 = pk(v1.x,v1.y), p3 = pk(v1.z,v1.w);
    uint32_t p4 = pk(v2.x,v2.y), p5 = pk(v2.z,v2.w);
    uint32_t p6 = pk(v3.x,v3.y), p7 = pk(v3.z,v3.w);
    uint4* dst = (uint4*)(g_xeb + ((size_t)(s*32 + c)*64 + b)*8);
    dst[0] = make_uint4(p0,p4,p1,p5);
    dst[1] = make_uint4(p2,p6,p3,p7);
}

// ---------------------------------------------------------------------------
// Input-projection GEMM (bf16 m16n8k16), both directions via blockIdx.z.
// C_T[s][n][b] = sum_h A[s*64+b][h]*W[n][h] + bx[n] + bh[n]
// M=32768, N=2048, K=512. BM=BN=128, BK=32. 8 warps = 4(m) x 2(n), warp 32x64.
// A read as pre-packed bf16 (pure copy to smem); W converted fp32->bf16 at stage.
// ---------------------------------------------------------------------------
#define ROWP 12        // smem row pitch in words (8 used + 4 pad, uint4-aligned)
#define CHP  (128*ROWP)

__global__ void __launch_bounds__(256)
gemm_xproj(int selA,
           const float* __restrict__ WF, const float* __restrict__ bxF,
           const float* __restrict__ bhF,
           const float* __restrict__ WB, const float* __restrict__ bxB,
           const float* __restrict__ bhB)
{
    __shared__ uint32_t sA[2*CHP];
    __shared__ uint32_t sB[2*CHP];

    int d = blockIdx.z;
    const uint32_t* A = (selA == 0) ? g_xeb : (d ? g_hsb_b : g_hsb_f);
    const float* W   = d ? WB  : WF;
    const float* bia = d ? bxB : bxF;
    const float* bib = d ? bhB : bhF;
    float* C = d ? g_xp_b : g_xp_f;

    int m0 = blockIdx.y * 128;
    int n0 = blockIdx.x * 128;
    int tid = threadIdx.x;
    int wid = tid >> 5, lane = tid & 31;
    int g = lane >> 2, tq = lane & 3;
    int wm = wid >> 1, wn = wid & 1;          // warp tile 32(m) x 64(n)

    float acc[2][8][4];
    #pragma unroll
    for (int mf = 0; mf < 2; mf++)
        #pragma unroll
        for (int nt = 0; nt < 8; nt++)
            #pragma unroll
            for (int q = 0; q < 4; q++) acc[mf][nt][q] = 0.f;

    const int row = tid >> 1, ch = tid & 1;   // staging unit (fixed per thread)
    const int ms = (m0 + row) >> 6, mb = (m0 + row) & 63;

    for (int it = 0; it < 16; it++) {
        int k0 = it * 32;
        // stage A: pure uint4 copy of pre-packed bf16
        {
            const uint4* src = (const uint4*)(A + ((size_t)(ms*32 + (k0>>4) + ch)*64 + mb)*8);
            uint4* dst = (uint4*)(sA + ch*CHP + row*ROWP);
            dst[0] = src[0];
            dst[1] = src[1];
        }
        // stage B: fp32 -> bf16 pair-permute
        {
            const float* src = W + (size_t)(n0+row)*HID + k0 + ch*16;
            float4 v0 = *(const float4*)src;
            float4 v1 = *(const float4*)(src + 4);
            float4 v2 = *(const float4*)(src + 8);
            float4 v3 = *(const float4*)(src + 12);
            uint32_t p0 = pk(v0.x,v0.y), p1 = pk(v0.z,v0.w);
            uint32_t p2 = pk(v1.x,v1.y), p3 = pk(v1.z,v1.w);
            uint32_t p4 = pk(v2.x,v2.y), p5 = pk(v2.z,v2.w);
            uint32_t p6 = pk(v3.x,v3.y), p7 = pk(v3.z,v3.w);
            uint4* dst = (uint4*)(sB + ch*CHP + row*ROWP);
            dst[0] = make_uint4(p0,p4,p1,p5);
            dst[1] = make_uint4(p2,p6,p3,p7);
        }
        __syncthreads();

        #pragma unroll
        for (int c2 = 0; c2 < 2; c2++) {
            uint32_t a[2][4];
            #pragma unroll
            for (int mf = 0; mf < 2; mf++) {
                int r0 = wm*32 + mf*16 + g;
                uint2 lo = *(const uint2*)(sA + c2*CHP + r0*ROWP + 2*tq);
                uint2 hi = *(const uint2*)(sA + c2*CHP + (r0+8)*ROWP + 2*tq);
                a[mf][0] = lo.x; a[mf][1] = hi.x; a[mf][2] = lo.y; a[mf][3] = hi.y;
            }
            #pragma unroll
            for (int nt = 0; nt < 8; nt++) {
                int r = wn*64 + nt*8 + g;
                uint2 bb = *(const uint2*)(sB + c2*CHP + r*ROWP + 2*tq);
                mma16(acc[0][nt], a[0], bb.x, bb.y);
                mma16(acc[1][nt], a[1], bb.x, bb.y);
            }
        }
        __syncthreads();
    }

    // epilogue: bias + store transposed C[s][n][b]
    #pragma unroll
    for (int mf = 0; mf < 2; mf++) {
        int m = m0 + wm*32 + mf*16 + g;
        int s1 = m >> 6,     b1 = m & 63;
        int s2 = (m+8) >> 6, b2 = (m+8) & 63;
        #pragma unroll
        for (int nt = 0; nt < 8; nt++) {
            int n = n0 + wn*64 + nt*8 + 2*tq;
            float bv0 = bia[n]   + bib[n];
            float bv1 = bia[n+1] + bib[n+1];
            C[((size_t)s1*GATES + n  )*64 + b1] = acc[mf][nt][0] + bv0;
            C[((size_t)s1*GATES + n+1)*64 + b1] = acc[mf][nt][1] + bv1;
            C[((size_t)s2*GATES + n  )*64 + b2] = acc[mf][nt][2] + bv0;
            C[((size_t)s2*GATES + n+1)*64 + b2] = acc[mf][nt][3] + bv1;
        }
    }
}

// ---------------------------------------------------------------------------
// Persistent LSTM layer (bf16 tensor cores), both directions, all 512 steps.
// 128 blocks: dir = blk>>6, kc = blk&63 -> 32 gate-rows (4 gates x 8 hid cols).
// 8 warps = 8 disjoint k-slices of 64; warp handles all 32 m rows (2 m-frags).
// Weights in registers (32 regs). h fragments ld.global.cg'd straight from the
// bf16 pair-permuted global h buffer (no smem staging). 8-way k-partial reduce
// via smem, fused pointwise (c in registers), h written back packed bf16.
// ---------------------------------------------------------------------------
#define SGP 68
#define SMEM_LSTM (8*32*SGP*4)     // 69632 bytes

__global__ void __launch_bounds__(256, 1)
lstm_layer(const float* __restrict__ WhF, const float* __restrict__ WhB,
           int rev_b, int store_hs)
{
    extern __shared__ float sG[];          // [ks(8)][row(32)][SGP]

    const int dir = blockIdx.x >> 6;
    const int kc  = blockIdx.x & 63;
    const int tid = threadIdx.x;
    const int wid = tid >> 5, lane = tid & 31;   // wid = k-slice
    const int g = lane >> 2, tq = lane & 3;
    const unsigned nb = gridDim.x;

    const float* Wh  = dir ? WhB : WhF;
    const float* xpb = dir ? g_xp_b : g_xp_f;
    uint32_t*    hsb = dir ? g_hsb_b : g_hsb_f;

    // --- preload weights as bf16 A-fragments (once per layer) ---
    const float* wr[4];
    #pragma unroll
    for (int i = 0; i < 4; i++) {
        int lr = i*8 + g;                                  // local rows g,g+8,g+16,g+24
        wr[i] = Wh + (size_t)((lr >> 3)*512 + kc*8 + (lr & 7)) * HID;
    }
    uint32_t aw[4][2][4];
    #pragma unroll
    for (int kt = 0; kt < 4; kt++) {
        int kb = wid*64 + kt*16 + 2*tq;
        #pragma unroll
        for (int mf = 0; mf < 2; mf++) {
            aw[kt][mf][0] = pk(wr[2*mf  ][kb],   wr[2*mf  ][kb+1]);
            aw[kt][mf][1] = pk(wr[2*mf+1][kb],   wr[2*mf+1][kb+1]);
            aw[kt][mf][2] = pk(wr[2*mf  ][kb+8], wr[2*mf  ][kb+9]);
            aw[kt][mf][3] = pk(wr[2*mf+1][kb+8], wr[2*mf+1][kb+9]);
        }
    }

    // --- clear owned slice of h buffer 0 ---
    {
        int b = tid >> 2, i = tid & 3;
        int pos = 2*i + (kc & 1);
        g_hb[(((0*2 + dir)*32 + (kc >> 1))*64 + b)*8 + pos] = 0;
    }

    // pointwise mapping (static across t -> c in registers)
    const int pb = tid >> 2;              // batch 0..63
    const int j0 = (tid & 3) * 2;         // hidden-col pair base 0,2,4,6
    float creg[2] = {0.f, 0.f};

    grid_bar(nb);

    for (int t = 0; t < SEQ; t++) {
        int xrow = dir ? (rev_b ? (SEQ-1-t) : t) : t;
        const float*    xp    = xpb + (size_t)xrow * (GATES*64);
        const uint32_t* hbin  = g_hb + (size_t)(((t  )&1)*2 + dir)*32*512;
        uint32_t*       hbout = g_hb + (size_t)(((t+1)&1)*2 + dir)*32*512;

        float acc[2][8][4];
        #pragma unroll
        for (int mf = 0; mf < 2; mf++)
            #pragma unroll
            for (int nt = 0; nt < 8; nt++)
                #pragma unroll
                for (int q = 0; q < 4; q++) acc[mf][nt][q] = 0.f;

        // --- MMA: fragments straight from L2 (coalesced 256B per frag) ---
        #pragma unroll
        for (int kt = 0; kt < 4; kt++) {
            const uint32_t* base = hbin + (wid*4 + kt)*512;
            #pragma unroll
            for (int nt = 0; nt < 8; nt++) {
                uint2 bb = ldcg_u2(base + (nt*8 + g)*8 + 2*tq);
                mma16(acc[0][nt], aw[kt][0], bb.x, bb.y);
                mma16(acc[1][nt], aw[kt][1], bb.x, bb.y);
            }
        }

        // --- write k-partials ---
        #pragma unroll
        for (int mf = 0; mf < 2; mf++)
            #pragma unroll
            for (int nt = 0; nt < 8; nt++) {
                int b = nt*8 + 2*tq;
                *(float2*)&sG[(wid*32 + mf*16 + g    )*SGP + b] =
                    make_float2(acc[mf][nt][0], acc[mf][nt][1]);
                *(float2*)&sG[(wid*32 + mf*16 + g + 8)*SGP + b] =
                    make_float2(acc[mf][nt][2], acc[mf][nt][3]);
            }
        __syncthreads();

        // --- pointwise: thread owns cells (j0, pb) and (j0+1, pb) ---
        float hv[2];
        #pragma unroll
        for (int r = 0; r < 2; r++) {
            int j = j0 + r;
            int kg = kc*8 + j;
            float v[4];
            #pragma unroll
            for (int gate = 0; gate < 4; gate++) {
                float s = xp[((gate << 9) + kg)*64 + pb];
                #pragma unroll
                for (int ks = 0; ks < 8; ks++)
                    s += sG[(ks*32 + gate*8 + j)*SGP + pb];
                v[gate] = s;
            }
            float f  = 1.f/(1.f + expf(-v[0]));
            float ii = 1.f/(1.f + expf(-v[1]));
            float gg = tanhf(v[2]);
            float o  = 1.f/(1.f + expf(-v[3]));
            float c = f*creg[r] + ii*gg;
            creg[r] = c;
            hv[r] = o*tanhf(c);
            if (t == SEQ-1)
                g_h[dir*HB + pb*HID + kg] = hv[r];
        }
        // pack pair -> permuted bf16 global h (+ hs history for layer-1 GEMM)
        {
            uint32_t w = pk(hv[0], hv[1]);
            int pos = j0 + (kc & 1);
            hbout[((kc >> 1)*64 + pb)*8 + pos] = w;
            if (store_hs)
                hsb[((size_t)(t*32 + (kc >> 1))*64 + pb)*8 + pos] = w;
        }
        grid_bar(nb);
    }
}

// ---------------------------------------------------------------------------
// Final FC + sigmoid. Final fp32 states in g_h[dir][b][k].
// ---------------------------------------------------------------------------
__global__ void final_fc(const float* __restrict__ fcw, const float* __restrict__ fcb,
                         float* __restrict__ out)
{
    int b = blockIdx.x;
    const float* hf = g_h + b*HID;
    const float* hb = g_h + HB + b*HID;
    float s = 0.f;
    for (int k = threadIdx.x; k < HID; k += 128)
        s += hf[k]*fcw[k] + hb[k]*fcw[HID + k];
    #pragma unroll
    for (int off = 16; off > 0; off >>= 1)
        s += __shfl_xor_sync(0xFFFFFFFFu, s, off);
    __shared__ float red[4];
    int warp = threadIdx.x >> 5, lane = threadIdx.x & 31;
    if (lane == 0) red[warp] = s;
    __syncthreads();
    if (threadIdx.x == 0) {
        float tot = red[0] + red[1] + red[2] + red[3] + fcb[0];
        out[b] = 1.f/(1.f + expf(-tot));
    }
}

// ---------------------------------------------------------------------------
// Launch sequence: 6 graph nodes.
// ---------------------------------------------------------------------------
extern "C" void kernel_launch(void* const* d_in, const int* in_sizes, int n_in,
                              void* d_out, int out_size)
{
    const int*   x    = (const int*)  d_in[0];
    const float* emb  = (const float*)d_in[1];
    const float* Wx_f = (const float*)d_in[2];
    const float* bx_f = (const float*)d_in[3];
    const float* Wh_f = (const float*)d_in[4];
    const float* bh_f = (const float*)d_in[5];
    const float* Wx_b = (const float*)d_in[6];
    const float* bx_b = (const float*)d_in[7];
    const float* Wh_b = (const float*)d_in[8];
    const float* bh_b = (const float*)d_in[9];
    const float* fcw  = (const float*)d_in[10];
    const float* fcb  = (const float*)d_in[11];
    float* out = (float*)d_out;

    const int WL = 4*HID*HID;
    const int BL = 4*HID;

    cudaFuncSetAttribute(lstm_layer, cudaFuncAttributeMaxDynamicSharedMemorySize, SMEM_LSTM);

    dim3 ggrid(GATES/128, MROWS/128, 2);   // (16, 256, 2)

    // 1. embedding -> packed bf16 xe
    embed_kernel<<<MROWS/8, 256>>>(x, emb);

    // 2. layer-0 input projections (A = xe), bias = bx + bh
    gemm_xproj<<<ggrid, 256>>>(0, Wx_f, bx_f, bh_f, Wx_b, bx_b, bh_b);

    // 3. layer-0 recurrence (backward reads xp row 511-t, store hs)
    lstm_layer<<<NBLK, 256, SMEM_LSTM>>>(Wh_f, Wh_b, 1, 1);

    // 4. layer-1 input projections (A = packed bf16 hs per dir)
    gemm_xproj<<<ggrid, 256>>>(1, Wx_f + WL, bx_f + BL, bh_f + BL,
                                  Wx_b + WL, bx_b + BL, bh_b + BL);

    // 5. layer-1 recurrence (both dirs read xp row t)
    lstm_layer<<<NBLK, 256, SMEM_LSTM>>>(Wh_f + WL, Wh_b + WL, 0, 0);

    // 6. final FC + sigmoid
    final_fc<<<BATCH, 128>>>(fcw, fcb, out);
}

// round 6
// speedup vs baseline: 4.6920x; 1.3462x over previous
#include <cuda_runtime.h>
#include <math.h>
#include <stdint.h>

// Problem constants
#define BATCH 64
#define SEQ   512
#define HID   512
#define GATES 2048              // 4*HID
#define MROWS (SEQ*BATCH)       // 32768
#define HB    (BATCH*HID)       // one (dir) h plane
#define NBLK  128               // persistent grid size (64 per direction)

// ---------------------------------------------------------------------------
// Scratch (static __device__ globals; no runtime allocation)
// bf16 pair-permuted layout: a row of 512 k-values = 32 chunks of 16.
// Chunk = 8 uint32 words [p0,p4,p1,p5,p2,p6,p3,p7], p_i = pack(k=2i,k=2i+1).
// uint2 read at word 2*tq yields exactly the m16n8k16 fragment halves.
// ---------------------------------------------------------------------------
__device__ uint32_t g_xeb  [(size_t)SEQ*32*BATCH*8];   // [s][chunk][b][8]
__device__ uint32_t g_hsb_f[(size_t)SEQ*32*BATCH*8];   // [t][chunk][b][8]
__device__ uint32_t g_hsb_b[(size_t)SEQ*32*BATCH*8];
__device__ uint32_t g_hb   [2*2*32*BATCH*8];           // [buf][dir][chunk][b][8]
__device__ float    g_xp_f [(size_t)SEQ*GATES*BATCH];  // [s][gk][b]
__device__ float    g_xp_b [(size_t)SEQ*GATES*BATCH];
__device__ float    g_h    [2*HB];                     // [dir][b][k] (final step)

__device__ unsigned g_cnt[64];   // per-dir arrival counters at [dir*32]
__device__ unsigned g_gen[64];   // per-dir generation       at [dir*32]

// ---------------------------------------------------------------------------
// helpers
// ---------------------------------------------------------------------------
__device__ __forceinline__ uint32_t pk(float lo, float hi)
{
    uint32_t r;
    asm("cvt.rn.bf16x2.f32 %0, %1, %2;" : "=r"(r) : "f"(hi), "f"(lo));
    return r;
}

// D(16x8) += A(16x16) * B(16x8), bf16 inputs, fp32 accum.
__device__ __forceinline__ void mma16(float* c, const uint32_t* a, uint32_t b0, uint32_t b1)
{
    asm volatile(
        "mma.sync.aligned.m16n8k16.row.col.f32.bf16.bf16.f32 "
        "{%0,%1,%2,%3},{%4,%5,%6,%7},{%8,%9},{%0,%1,%2,%3};"
        : "+f"(c[0]), "+f"(c[1]), "+f"(c[2]), "+f"(c[3])
        : "r"(a[0]), "r"(a[1]), "r"(a[2]), "r"(a[3]), "r"(b0), "r"(b1));
}

__device__ __forceinline__ uint2 ldcg_u2(const uint32_t* p)
{
    uint2 v;
    asm volatile("ld.global.cg.v2.u32 {%0,%1}, [%2];"
                 : "=r"(v.x), "=r"(v.y) : "l"(p));
    return v;
}

// ---------------------------------------------------------------------------
// Split grid barrier, per direction (64 participants).
// Release-atomic arrive by thread 0 (bar.sync extends coverage to the whole
// block's prior stores per the PTX memory model); acquire-load spin.
// Generation compared against the kernel-entry snapshot -> replay-safe.
// ---------------------------------------------------------------------------
__device__ __forceinline__ void bar_arrive(unsigned* cnt, unsigned* gen, unsigned nb)
{
    __syncthreads();
    if (threadIdx.x == 0) {
        unsigned old;
        asm volatile("atom.release.gpu.global.add.u32 %0, [%1], 1;"
                     : "=r"(old) : "l"(cnt) : "memory");
        if (old == nb - 1u) {
            asm volatile("st.relaxed.gpu.global.u32 [%0], 0;" :: "l"(cnt) : "memory");
            asm volatile("red.release.gpu.global.add.u32 [%0], 1;" :: "l"(gen) : "memory");
        }
    }
}

__device__ __forceinline__ void bar_wait(unsigned* gen, unsigned target)
{
    if (threadIdx.x == 0) {
        unsigned v;
        do {
            asm volatile("ld.acquire.gpu.global.u32 %0, [%1];"
                         : "=r"(v) : "l"(gen) : "memory");
        } while ((int)(v - target) < 0);
    }
    __syncthreads();
}

// ---------------------------------------------------------------------------
// Embedding gather -> bf16 pair-permuted xe.
// ---------------------------------------------------------------------------
__global__ void embed_kernel(const int* __restrict__ x, const float* __restrict__ emb)
{
    int row = blockIdx.x*8 + (threadIdx.x >> 5);    // s*64 + b
    int c   = threadIdx.x & 31;                     // chunk
    int s = row >> 6, b = row & 63;
    int idx = x[b*SEQ + s];
    const float* src = emb + (size_t)idx*HID + c*16;
    float4 v0 = *(const float4*)src;
    float4 v1 = *(const float4*)(src + 4);
    float4 v2 = *(const float4*)(src + 8);
    float4 v3 = *(const float4*)(src + 12);
    uint32_t p0 = pk(v0.x,v0.y), p1 = pk(v0.z,v0.w);
    uint32_t p2 = pk(v1.x,v1.y), p3 = pk(v1.z,v1.w);
    uint32_t p4 = pk(v2.x,v2.y), p5 = pk(v2.z,v2.w);
    uint32_t p6 = pk(v3.x,v3.y), p7 = pk(v3.z,v3.w);
    uint4* dst = (uint4*)(g_xeb + ((size_t)(s*32 + c)*64 + b)*8);
    dst[0] = make_uint4(p0,p4,p1,p5);
    dst[1] = make_uint4(p2,p6,p3,p7);
}

// ---------------------------------------------------------------------------
// Input-projection GEMM (bf16 m16n8k16), both directions via blockIdx.z.
// C_T[s][n][b] = sum_h A[s*64+b][h]*W[n][h] + bx[n] + bh[n]
// M=32768, N=2048, K=512. BM=BN=128, BK=32. 8 warps = 4(m) x 2(n), warp 32x64.
// A fragments loaded DIRECTLY from pre-packed global bf16 (no smem staging,
// fully coalesced 256B per fragment). B (fp32 weights) staged to smem with
// cvt+pair-permute, double-buffered.
// ---------------------------------------------------------------------------
#define ROWP 12        // smem row pitch in words (8 used + 4 pad)
#define CHP  (128*ROWP)

__global__ void __launch_bounds__(256, 2)
gemm_xproj(int selA,
           const float* __restrict__ WF, const float* __restrict__ bxF,
           const float* __restrict__ bhF,
           const float* __restrict__ WB, const float* __restrict__ bxB,
           const float* __restrict__ bhB)
{
    __shared__ uint32_t sB[2][2*CHP];

    int d = blockIdx.z;
    const uint32_t* A = (selA == 0) ? g_xeb : (d ? g_hsb_b : g_hsb_f);
    const float* W   = d ? WB  : WF;
    const float* bia = d ? bxB : bxF;
    const float* bib = d ? bhB : bhF;
    float* C = d ? g_xp_b : g_xp_f;

    int m0 = blockIdx.y * 128;
    int n0 = blockIdx.x * 128;
    int tid = threadIdx.x;
    int wid = tid >> 5, lane = tid & 31;
    int g = lane >> 2, tq = lane & 3;
    int wm = wid >> 1, wn = wid & 1;          // warp tile 32(m) x 64(n)

    float acc[2][8][4];
    #pragma unroll
    for (int mf = 0; mf < 2; mf++)
        #pragma unroll
        for (int nt = 0; nt < 8; nt++)
            #pragma unroll
            for (int q = 0; q < 4; q++) acc[mf][nt][q] = 0.f;

    // A fragment base offsets (words): chunk stride is 512 words
    size_t abase[2];
    #pragma unroll
    for (int mf = 0; mf < 2; mf++) {
        int r0 = wm*32 + mf*16 + g;
        int m = m0 + r0;
        abase[mf] = ((size_t)(m >> 6))*32*512 + (size_t)(m & 63)*8 + 2*tq;
    }

    const int srow = tid >> 1, sch = tid & 1;
    const float* wsrc0 = W + (size_t)(n0 + srow)*HID + sch*16;

    auto stageB = [&](int it, int buf) {
        const float* src = wsrc0 + it*32;
        float4 v0 = *(const float4*)src;
        float4 v1 = *(const float4*)(src + 4);
        float4 v2 = *(const float4*)(src + 8);
        float4 v3 = *(const float4*)(src + 12);
        uint32_t p0 = pk(v0.x,v0.y), p1 = pk(v0.z,v0.w);
        uint32_t p2 = pk(v1.x,v1.y), p3 = pk(v1.z,v1.w);
        uint32_t p4 = pk(v2.x,v2.y), p5 = pk(v2.z,v2.w);
        uint32_t p6 = pk(v3.x,v3.y), p7 = pk(v3.z,v3.w);
        uint4* dst = (uint4*)(&sB[buf][sch*CHP + srow*ROWP]);
        dst[0] = make_uint4(p0,p4,p1,p5);
        dst[1] = make_uint4(p2,p6,p3,p7);
    };

    stageB(0, 0);
    __syncthreads();
    int buf = 0;

    for (int it = 0; it < 16; it++) {
        // A fragment loads straight from global (L1-cached; warp pair shares)
        uint2 alo[2][2], ahi[2][2];
        #pragma unroll
        for (int c2 = 0; c2 < 2; c2++)
            #pragma unroll
            for (int mf = 0; mf < 2; mf++) {
                const uint32_t* pa = A + abase[mf] + (size_t)(it*2 + c2)*512;
                alo[c2][mf] = *(const uint2*)pa;
                ahi[c2][mf] = *(const uint2*)(pa + 64);   // rows +8 -> b+8
            }
        if (it < 15) stageB(it+1, buf^1);

        #pragma unroll
        for (int c2 = 0; c2 < 2; c2++) {
            uint32_t a[2][4];
            #pragma unroll
            for (int mf = 0; mf < 2; mf++) {
                a[mf][0] = alo[c2][mf].x; a[mf][1] = ahi[c2][mf].x;
                a[mf][2] = alo[c2][mf].y; a[mf][3] = ahi[c2][mf].y;
            }
            #pragma unroll
            for (int nt = 0; nt < 8; nt++) {
                int r = wn*64 + nt*8 + g;
                uint2 bb = *(const uint2*)(&sB[buf][c2*CHP + r*ROWP + 2*tq]);
                mma16(acc[0][nt], a[0], bb.x, bb.y);
                mma16(acc[1][nt], a[1], bb.x, bb.y);
            }
        }
        __syncthreads();
        buf ^= 1;
    }

    // epilogue: bias + store transposed C[s][n][b]
    #pragma unroll
    for (int mf = 0; mf < 2; mf++) {
        int m = m0 + wm*32 + mf*16 + g;
        int s1 = m >> 6,     b1 = m & 63;
        int s2 = (m+8) >> 6, b2 = (m+8) & 63;
        #pragma unroll
        for (int nt = 0; nt < 8; nt++) {
            int n = n0 + wn*64 + nt*8 + 2*tq;
            float bv0 = bia[n]   + bib[n];
            float bv1 = bia[n+1] + bib[n+1];
            C[((size_t)s1*GATES + n  )*64 + b1] = acc[mf][nt][0] + bv0;
            C[((size_t)s1*GATES + n+1)*64 + b1] = acc[mf][nt][1] + bv1;
            C[((size_t)s2*GATES + n  )*64 + b2] = acc[mf][nt][2] + bv0;
            C[((size_t)s2*GATES + n+1)*64 + b2] = acc[mf][nt][3] + bv1;
        }
    }
}

// ---------------------------------------------------------------------------
// Persistent LSTM layer (bf16 tensor cores), both directions, all 512 steps.
// 128 blocks: dir = blk>>6, kc = blk&63 -> 32 gate-rows (4 gates x 8 hid cols).
// 8 warps = 8 disjoint k-slices of 64. Weights in registers. h fragments
// ld.global.cg'd from the bf16 pair-permuted global h buffer. Per-dir split
// barrier; xp for step t+1 prefetched into registers between arrive and wait.
// ---------------------------------------------------------------------------
#define SGP 68
#define SMEM_LSTM (8*32*SGP*4)     // 69632 bytes

__global__ void __launch_bounds__(256, 1)
lstm_layer(const float* __restrict__ WhF, const float* __restrict__ WhB,
           int rev_b, int store_hs)
{
    extern __shared__ float sG[];          // [ks(8)][row(32)][SGP]

    const int dir = blockIdx.x >> 6;
    const int kc  = blockIdx.x & 63;
    const int tid = threadIdx.x;
    const int wid = tid >> 5, lane = tid & 31;   // wid = k-slice
    const int g = lane >> 2, tq = lane & 3;

    unsigned* cnt = &g_cnt[dir*32];
    unsigned* gen = &g_gen[dir*32];
    const unsigned gbase = *(volatile unsigned*)gen;   // stable pre-kernel value
    unsigned phase = 0;

    const float* Wh  = dir ? WhB : WhF;
    const float* xpb = dir ? g_xp_b : g_xp_f;
    uint32_t*    hsb = dir ? g_hsb_b : g_hsb_f;

    // --- preload weights as bf16 A-fragments (once per layer) ---
    const float* wr[4];
    #pragma unroll
    for (int i = 0; i < 4; i++) {
        int lr = i*8 + g;
        wr[i] = Wh + (size_t)((lr >> 3)*512 + kc*8 + (lr & 7)) * HID;
    }
    uint32_t aw[4][2][4];
    #pragma unroll
    for (int kt = 0; kt < 4; kt++) {
        int kb = wid*64 + kt*16 + 2*tq;
        #pragma unroll
        for (int mf = 0; mf < 2; mf++) {
            aw[kt][mf][0] = pk(wr[2*mf  ][kb],   wr[2*mf  ][kb+1]);
            aw[kt][mf][1] = pk(wr[2*mf+1][kb],   wr[2*mf+1][kb+1]);
            aw[kt][mf][2] = pk(wr[2*mf  ][kb+8], wr[2*mf  ][kb+9]);
            aw[kt][mf][3] = pk(wr[2*mf+1][kb+8], wr[2*mf+1][kb+9]);
        }
    }

    // --- clear owned slice of h buffer 0 ---
    {
        int b = tid >> 2, i = tid & 3;
        int pos = 2*i + (kc & 1);
        g_hb[(((0*2 + dir)*32 + (kc >> 1))*64 + b)*8 + pos] = 0;
    }

    // pointwise mapping (static across t -> c in registers)
    const int pb = tid >> 2;              // batch 0..63
    const int j0 = (tid & 3) * 2;         // hidden-col pair base 0,2,4,6
    float creg[2] = {0.f, 0.f};
    float xr[2][4];                       // prefetched xp for current step

    // initial barrier; prefetch xp(0) inside the wait slack
    phase++;
    bar_arrive(cnt, gen, 64);
    {
        int xrow0 = (dir && rev_b) ? (SEQ-1) : 0;
        const float* xp0 = xpb + (size_t)xrow0 * (GATES*64);
        #pragma unroll
        for (int r = 0; r < 2; r++)
            #pragma unroll
            for (int gate = 0; gate < 4; gate++)
                xr[r][gate] = __ldcg(&xp0[((gate << 9) + kc*8 + j0 + r)*64 + pb]);
    }
    bar_wait(gen, gbase + phase);

    for (int t = 0; t < SEQ; t++) {
        const uint32_t* hbin  = g_hb + (size_t)(((t  )&1)*2 + dir)*32*512;
        uint32_t*       hbout = g_hb + (size_t)(((t+1)&1)*2 + dir)*32*512;

        float acc[2][8][4];
        #pragma unroll
        for (int mf = 0; mf < 2; mf++)
            #pragma unroll
            for (int nt = 0; nt < 8; nt++)
                #pragma unroll
                for (int q = 0; q < 4; q++) acc[mf][nt][q] = 0.f;

        // --- MMA: h fragments straight from L2 (coalesced 256B per frag) ---
        #pragma unroll
        for (int kt = 0; kt < 4; kt++) {
            const uint32_t* base = hbin + (wid*4 + kt)*512;
            #pragma unroll
            for (int nt = 0; nt < 8; nt++) {
                uint2 bb = ldcg_u2(base + (nt*8 + g)*8 + 2*tq);
                mma16(acc[0][nt], aw[kt][0], bb.x, bb.y);
                mma16(acc[1][nt], aw[kt][1], bb.x, bb.y);
            }
        }

        // --- write k-partials ---
        #pragma unroll
        for (int mf = 0; mf < 2; mf++)
            #pragma unroll
            for (int nt = 0; nt < 8; nt++) {
                int b = nt*8 + 2*tq;
                *(float2*)&sG[(wid*32 + mf*16 + g    )*SGP + b] =
                    make_float2(acc[mf][nt][0], acc[mf][nt][1]);
                *(float2*)&sG[(wid*32 + mf*16 + g + 8)*SGP + b] =
                    make_float2(acc[mf][nt][2], acc[mf][nt][3]);
            }
        __syncthreads();

        // --- pointwise: thread owns cells (j0, pb) and (j0+1, pb) ---
        float hv[2];
        #pragma unroll
        for (int r = 0; r < 2; r++) {
            int j = j0 + r;
            int kg = kc*8 + j;
            float v[4];
            #pragma unroll
            for (int gate = 0; gate < 4; gate++) {
                float s = xr[r][gate];
                #pragma unroll
                for (int ks = 0; ks < 8; ks++)
                    s += sG[(ks*32 + gate*8 + j)*SGP + pb];
                v[gate] = s;
            }
            float f  = 1.f/(1.f + expf(-v[0]));
            float ii = 1.f/(1.f + expf(-v[1]));
            float gg = tanhf(v[2]);
            float o  = 1.f/(1.f + expf(-v[3]));
            float c = f*creg[r] + ii*gg;
            creg[r] = c;
            hv[r] = o*tanhf(c);
            if (t == SEQ-1)
                g_h[dir*HB + pb*HID + kg] = hv[r];
        }
        // pack pair -> permuted bf16 global h (+ hs history for layer-1 GEMM)
        {
            uint32_t w = pk(hv[0], hv[1]);
            int pos = j0 + (kc & 1);
            hbout[((kc >> 1)*64 + pb)*8 + pos] = w;
            if (store_hs)
                hsb[((size_t)(t*32 + (kc >> 1))*64 + pb)*8 + pos] = w;
        }

        // --- barrier with xp(t+1) prefetch hidden in the wait slack ---
        phase++;
        bar_arrive(cnt, gen, 64);
        if (t + 1 < SEQ) {
            int tn = t + 1;
            int xrow = (dir && rev_b) ? (SEQ-1-tn) : tn;
            const float* xpn = xpb + (size_t)xrow * (GATES*64);
            #pragma unroll
            for (int r = 0; r < 2; r++)
                #pragma unroll
                for (int gate = 0; gate < 4; gate++)
                    xr[r][gate] = __ldcg(&xpn[((gate << 9) + kc*8 + j0 + r)*64 + pb]);
        }
        bar_wait(gen, gbase + phase);
    }
}

// ---------------------------------------------------------------------------
// Final FC + sigmoid. Final fp32 states in g_h[dir][b][k].
// ---------------------------------------------------------------------------
__global__ void final_fc(const float* __restrict__ fcw, const float* __restrict__ fcb,
                         float* __restrict__ out)
{
    int b = blockIdx.x;
    const float* hf = g_h + b*HID;
    const float* hb = g_h + HB + b*HID;
    float s = 0.f;
    for (int k = threadIdx.x; k < HID; k += 128)
        s += hf[k]*fcw[k] + hb[k]*fcw[HID + k];
    #pragma unroll
    for (int off = 16; off > 0; off >>= 1)
        s += __shfl_xor_sync(0xFFFFFFFFu, s, off);
    __shared__ float red[4];
    int warp = threadIdx.x >> 5, lane = threadIdx.x & 31;
    if (lane == 0) red[warp] = s;
    __syncthreads();
    if (threadIdx.x == 0) {
        float tot = red[0] + red[1] + red[2] + red[3] + fcb[0];
        out[b] = 1.f/(1.f + expf(-tot));
    }
}

// ---------------------------------------------------------------------------
// Launch sequence: 6 graph nodes.
// ---------------------------------------------------------------------------
extern "C" void kernel_launch(void* const* d_in, const int* in_sizes, int n_in,
                              void* d_out, int out_size)
{
    const int*   x    = (const int*)  d_in[0];
    const float* emb  = (const float*)d_in[1];
    const float* Wx_f = (const float*)d_in[2];
    const float* bx_f = (const float*)d_in[3];
    const float* Wh_f = (const float*)d_in[4];
    const float* bh_f = (const float*)d_in[5];
    const float* Wx_b = (const float*)d_in[6];
    const float* bx_b = (const float*)d_in[7];
    const float* Wh_b = (const float*)d_in[8];
    const float* bh_b = (const float*)d_in[9];
    const float* fcw  = (const float*)d_in[10];
    const float* fcb  = (const float*)d_in[11];
    float* out = (float*)d_out;

    const int WL = 4*HID*HID;
    const int BL = 4*HID;

    cudaFuncSetAttribute(lstm_layer, cudaFuncAttributeMaxDynamicSharedMemorySize, SMEM_LSTM);

    dim3 ggrid(GATES/128, MROWS/128, 2);   // (16, 256, 2)

    // 1. embedding -> packed bf16 xe
    embed_kernel<<<MROWS/8, 256>>>(x, emb);

    // 2. layer-0 input projections (A = xe), bias = bx + bh
    gemm_xproj<<<ggrid, 256>>>(0, Wx_f, bx_f, bh_f, Wx_b, bx_b, bh_b);

    // 3. layer-0 recurrence (backward reads xp row 511-t, store hs)
    lstm_layer<<<NBLK, 256, SMEM_LSTM>>>(Wh_f, Wh_b, 1, 1);

    // 4. layer-1 input projections (A = packed bf16 hs per dir)
    gemm_xproj<<<ggrid, 256>>>(1, Wx_f + WL, bx_f + BL, bh_f + BL,
                                  Wx_b + WL, bx_b + BL, bh_b + BL);

    // 5. layer-1 recurrence (both dirs read xp row t)
    lstm_layer<<<NBLK, 256, SMEM_LSTM>>>(Wh_f + WL, Wh_b + WL, 0, 0);

    // 6. final FC + sigmoid
    final_fc<<<BATCH, 128>>>(fcw, fcb, out);
}

// round 7
// speedup vs baseline: 4.8667x; 1.0372x over previous
#include <cuda_runtime.h>
#include <math.h>
#include <stdint.h>

// Problem constants
#define BATCH 64
#define SEQ   512
#define HID   512
#define GATES 2048              // 4*HID
#define MROWS (SEQ*BATCH)       // 32768
#define HB    (BATCH*HID)       // one (dir) h plane
#define NBLK  128               // persistent grid size (64 per direction)

// ---------------------------------------------------------------------------
// Scratch (static __device__ globals; no runtime allocation)
// bf16 pair-permuted layout: a row of 512 k-values = 32 chunks of 16.
// Chunk = 8 uint32 words [p0,p4,p1,p5,p2,p6,p3,p7], p_i = pack(k=2i,k=2i+1).
// uint2 read at word 2*tq yields exactly the m16n8k16 fragment halves.
// ---------------------------------------------------------------------------
__device__ uint32_t g_xeb  [(size_t)SEQ*32*BATCH*8];   // [s][chunk][b][8]
__device__ uint32_t g_hsb_f[(size_t)SEQ*32*BATCH*8];   // [t][chunk][b][8]
__device__ uint32_t g_hsb_b[(size_t)SEQ*32*BATCH*8];
__device__ uint32_t g_hb   [2*2*32*BATCH*8];           // [buf][dir][chunk][b][8]
__device__ uint32_t g_wxb  [4][32][2048*8];            // [l*2+d][chunk][n*8+w]
__device__ float    g_xp_f [(size_t)SEQ*GATES*BATCH];  // [s][gk][b]
__device__ float    g_xp_b [(size_t)SEQ*GATES*BATCH];
__device__ float    g_h    [2*HB];                     // [dir][b][k] (final step)

__device__ unsigned g_slot [2][64];                    // per-dir barrier slots

// ---------------------------------------------------------------------------
// helpers
// ---------------------------------------------------------------------------
__device__ __forceinline__ uint32_t pk(float lo, float hi)
{
    uint32_t r;
    asm("cvt.rn.bf16x2.f32 %0, %1, %2;" : "=r"(r) : "f"(hi), "f"(lo));
    return r;
}

// D(16x8) += A(16x16) * B(16x8), bf16 inputs, fp32 accum.
__device__ __forceinline__ void mma16(float* c, const uint32_t* a, uint32_t b0, uint32_t b1)
{
    asm volatile(
        "mma.sync.aligned.m16n8k16.row.col.f32.bf16.bf16.f32 "
        "{%0,%1,%2,%3},{%4,%5,%6,%7},{%8,%9},{%0,%1,%2,%3};"
        : "+f"(c[0]), "+f"(c[1]), "+f"(c[2]), "+f"(c[3])
        : "r"(a[0]), "r"(a[1]), "r"(a[2]), "r"(a[3]), "r"(b0), "r"(b1));
}

__device__ __forceinline__ uint2 ldcg_u2(const uint32_t* p)
{
    uint2 v;
    asm volatile("ld.global.cg.v2.u32 {%0,%1}, [%2];"
                 : "=r"(v.x), "=r"(v.y) : "l"(p));
    return v;
}

__device__ __forceinline__ float tanh_ap(float x)
{
    float y;
    asm("tanh.approx.f32 %0, %1;" : "=f"(y) : "f"(x));
    return y;
}
__device__ __forceinline__ float sig_ap(float x)
{
    return fmaf(0.5f, tanh_ap(0.5f*x), 0.5f);
}

// ---------------------------------------------------------------------------
// Distributed per-direction grid barrier (64 blocks).
// Arrive: one release-store to the block's own slot (no contention).
// Wait: threads 0..63 each spin (acquire) on one slot, then bar.sync.
// ---------------------------------------------------------------------------
__device__ __forceinline__ void bar_arrive(unsigned* slots, int kc, unsigned tgt)
{
    __syncthreads();   // all block stores precede thread-0's release store
    if (threadIdx.x == 0)
        asm volatile("st.release.gpu.global.u32 [%0], %1;"
                     :: "l"(slots + kc), "r"(tgt) : "memory");
}

__device__ __forceinline__ void bar_wait(unsigned* slots, unsigned tgt)
{
    if (threadIdx.x < 64) {
        unsigned v;
        do {
            asm volatile("ld.acquire.gpu.global.u32 %0, [%1];"
                         : "=r"(v) : "l"(slots + threadIdx.x) : "memory");
        } while ((int)(v - tgt) < 0);
    }
    __syncthreads();
}

// ---------------------------------------------------------------------------
// Embedding gather -> bf16 pair-permuted xe.
// ---------------------------------------------------------------------------
__global__ void embed_kernel(const int* __restrict__ x, const float* __restrict__ emb)
{
    int row = blockIdx.x*8 + (threadIdx.x >> 5);    // s*64 + b
    int c   = threadIdx.x & 31;                     // chunk
    int s = row >> 6, b = row & 63;
    int idx = x[b*SEQ + s];
    const float* src = emb + (size_t)idx*HID + c*16;
    float4 v0 = *(const float4*)src;
    float4 v1 = *(const float4*)(src + 4);
    float4 v2 = *(const float4*)(src + 8);
    float4 v3 = *(const float4*)(src + 12);
    uint32_t p0 = pk(v0.x,v0.y), p1 = pk(v0.z,v0.w);
    uint32_t p2 = pk(v1.x,v1.y), p3 = pk(v1.z,v1.w);
    uint32_t p4 = pk(v2.x,v2.y), p5 = pk(v2.z,v2.w);
    uint32_t p6 = pk(v3.x,v3.y), p7 = pk(v3.z,v3.w);
    uint4* dst = (uint4*)(g_xeb + ((size_t)(s*32 + c)*64 + b)*8);
    dst[0] = make_uint4(p0,p4,p1,p5);
    dst[1] = make_uint4(p2,p6,p3,p7);
}

// ---------------------------------------------------------------------------
// Pre-pack Wx (all 4 layer/dir tensors) into bf16 pair-permuted global.
// Same packing as embed: [tensor][chunk][n*8+w].
// ---------------------------------------------------------------------------
__global__ void pack_w(const float* __restrict__ W0, const float* __restrict__ W1,
                       const float* __restrict__ W2, const float* __restrict__ W3)
{
    const float* Wt = (blockIdx.y == 0) ? W0 : (blockIdx.y == 1) ? W1
                    : (blockIdx.y == 2) ? W2 : W3;
    int n = blockIdx.x*8 + (threadIdx.x >> 5);
    int c = threadIdx.x & 31;
    const float* src = Wt + (size_t)n*HID + c*16;
    float4 v0 = *(const float4*)src;
    float4 v1 = *(const float4*)(src + 4);
    float4 v2 = *(const float4*)(src + 8);
    float4 v3 = *(const float4*)(src + 12);
    uint32_t p0 = pk(v0.x,v0.y), p1 = pk(v0.z,v0.w);
    uint32_t p2 = pk(v1.x,v1.y), p3 = pk(v1.z,v1.w);
    uint32_t p4 = pk(v2.x,v2.y), p5 = pk(v2.z,v2.w);
    uint32_t p6 = pk(v3.x,v3.y), p7 = pk(v3.z,v3.w);
    uint4* dst = (uint4*)(&g_wxb[blockIdx.y][c][n*8]);
    dst[0] = make_uint4(p0,p4,p1,p5);
    dst[1] = make_uint4(p2,p6,p3,p7);
}

// ---------------------------------------------------------------------------
// Input-projection GEMM (bf16 m16n8k16), smem-free: A and B fragments both
// loaded directly from pre-packed bf16 global (coalesced 256B per fragment).
// C_T[s][n][b] = sum_h A[s*64+b][h]*W[n][h] + bx[n] + bh[n]
// M=32768, N=2048, K=512. BM=BN=128. 8 warps = 4(m) x 2(n), warp 32x64.
// ---------------------------------------------------------------------------
__global__ void __launch_bounds__(256, 2)
gemm_xproj(int selA, int layer,
           const float* __restrict__ bxF, const float* __restrict__ bhF,
           const float* __restrict__ bxB, const float* __restrict__ bhB)
{
    int d = blockIdx.z;
    const uint32_t* A = (selA == 0) ? g_xeb : (d ? g_hsb_b : g_hsb_f);
    const uint32_t* B = &g_wxb[layer*2 + d][0][0];
    const float* bia = d ? bxB : bxF;
    const float* bib = d ? bhB : bhF;
    float* C = d ? g_xp_b : g_xp_f;

    int m0 = blockIdx.y * 128;
    int n0 = blockIdx.x * 128;
    int tid = threadIdx.x;
    int wid = tid >> 5, lane = tid & 31;
    int g = lane >> 2, tq = lane & 3;
    int wm = wid >> 1, wn = wid & 1;          // warp tile 32(m) x 64(n)

    float acc[2][8][4];
    #pragma unroll
    for (int mf = 0; mf < 2; mf++)
        #pragma unroll
        for (int nt = 0; nt < 8; nt++)
            #pragma unroll
            for (int q = 0; q < 4; q++) acc[mf][nt][q] = 0.f;

    // A fragment word offsets (chunk stride = 512 words)
    const uint32_t* Ap[2];
    #pragma unroll
    for (int mf = 0; mf < 2; mf++) {
        int m = m0 + wm*32 + mf*16 + g;
        Ap[mf] = A + ((size_t)(m >> 6))*32*512 + (size_t)(m & 63)*8 + 2*tq;
    }
    // B fragment base (chunk stride = 16384 words)
    const uint32_t* Bp = B + (size_t)(n0 + wn*64 + g)*8 + 2*tq;

    for (int it = 0; it < 16; it++) {
        #pragma unroll
        for (int c2 = 0; c2 < 2; c2++) {
            int ch = it*2 + c2;
            uint2 alo[2], ahi[2];
            #pragma unroll
            for (int mf = 0; mf < 2; mf++) {
                const uint32_t* pa = Ap[mf] + (size_t)ch*512;
                alo[mf] = *(const uint2*)pa;
                ahi[mf] = *(const uint2*)(pa + 64);   // rows +8
            }
            uint2 bb[8];
            #pragma unroll
            for (int nt = 0; nt < 8; nt++)
                bb[nt] = *(const uint2*)(Bp + (size_t)ch*16384 + nt*64);

            uint32_t a[2][4];
            #pragma unroll
            for (int mf = 0; mf < 2; mf++) {
                a[mf][0] = alo[mf].x; a[mf][1] = ahi[mf].x;
                a[mf][2] = alo[mf].y; a[mf][3] = ahi[mf].y;
            }
            #pragma unroll
            for (int nt = 0; nt < 8; nt++) {
                mma16(acc[0][nt], a[0], bb[nt].x, bb[nt].y);
                mma16(acc[1][nt], a[1], bb[nt].x, bb[nt].y);
            }
        }
    }

    // epilogue: bias + store transposed C[s][n][b]
    #pragma unroll
    for (int mf = 0; mf < 2; mf++) {
        int m = m0 + wm*32 + mf*16 + g;
        int s1 = m >> 6,     b1 = m & 63;
        int s2 = (m+8) >> 6, b2 = (m+8) & 63;
        #pragma unroll
        for (int nt = 0; nt < 8; nt++) {
            int n = n0 + wn*64 + nt*8 + 2*tq;
            float bv0 = bia[n]   + bib[n];
            float bv1 = bia[n+1] + bib[n+1];
            C[((size_t)s1*GATES + n  )*64 + b1] = acc[mf][nt][0] + bv0;
            C[((size_t)s1*GATES + n+1)*64 + b1] = acc[mf][nt][1] + bv1;
            C[((size_t)s2*GATES + n  )*64 + b2] = acc[mf][nt][2] + bv0;
            C[((size_t)s2*GATES + n+1)*64 + b2] = acc[mf][nt][3] + bv1;
        }
    }
}

// ---------------------------------------------------------------------------
// Persistent LSTM layer (bf16 tensor cores), both directions, all 512 steps.
// 128 blocks: dir = blk>>6, kc = blk&63 -> 32 gate-rows (4 gates x 8 hid cols).
// 8 warps = 4 k-slices (128 k each) x 2 n-halves (32 b each): disjoint h reads,
// 2 m-frags per warp. Weights in registers (64 regs). h fragments ld.global.cg
// from the bf16 pair-permuted global h buffer. 4-way k-partial reduce via smem,
// fused pointwise with tanh.approx activations, distributed slot barrier,
// xp(t+1) prefetched between barrier arrive and wait.
// ---------------------------------------------------------------------------
#define SGP 68

__global__ void __launch_bounds__(256, 1)
lstm_layer(const float* __restrict__ WhF, const float* __restrict__ WhB,
           int rev_b, int store_hs)
{
    __shared__ float sG[4*32*SGP];         // [ks(4)][row(32)][SGP]

    const int dir = blockIdx.x >> 6;
    const int kc  = blockIdx.x & 63;
    const int tid = threadIdx.x;
    const int wid = tid >> 5, lane = tid & 31;
    const int g = lane >> 2, tq = lane & 3;
    const int ks = wid >> 1;               // k-slice 0..3 (128 k each)
    const int nh = wid & 1;                // n-half 0..1 (32 b each)

    unsigned* slots = g_slot[dir];
    const unsigned pbase = *(volatile unsigned*)(slots + kc);  // own slot: stable
    unsigned tgt = pbase;

    const float* Wh  = dir ? WhB : WhF;
    const float* xpb = dir ? g_xp_b : g_xp_f;
    uint32_t*    hsb = dir ? g_hsb_b : g_hsb_f;

    // --- preload weights as bf16 A-fragments (once per layer) ---
    const float* wr[4];
    #pragma unroll
    for (int i = 0; i < 4; i++) {
        int lr = i*8 + g;                  // local rows g, g+8, g+16, g+24
        wr[i] = Wh + (size_t)((lr >> 3)*512 + kc*8 + (lr & 7)) * HID;
    }
    uint32_t aw[8][2][4];
    #pragma unroll
    for (int kt = 0; kt < 8; kt++) {
        int kb = ks*128 + kt*16 + 2*tq;
        #pragma unroll
        for (int mf = 0; mf < 2; mf++) {
            aw[kt][mf][0] = pk(wr[2*mf  ][kb],   wr[2*mf  ][kb+1]);
            aw[kt][mf][1] = pk(wr[2*mf+1][kb],   wr[2*mf+1][kb+1]);
            aw[kt][mf][2] = pk(wr[2*mf  ][kb+8], wr[2*mf  ][kb+9]);
            aw[kt][mf][3] = pk(wr[2*mf+1][kb+8], wr[2*mf+1][kb+9]);
        }
    }

    // --- clear owned slice of h buffer 0 ---
    {
        int b = tid >> 2, i = tid & 3;
        int pos = 2*i + (kc & 1);
        g_hb[(((0*2 + dir)*32 + (kc >> 1))*64 + b)*8 + pos] = 0;
    }

    // pointwise mapping (static across t -> c in registers)
    const int pb = tid >> 2;               // batch 0..63
    const int j0 = (tid & 3) * 2;          // hidden-col pair base 0,2,4,6
    float creg[2] = {0.f, 0.f};
    float xr[2][4];

    // initial barrier; prefetch xp(0) inside the wait slack
    tgt++;
    bar_arrive(slots, kc, tgt);
    {
        int xrow0 = (dir && rev_b) ? (SEQ-1) : 0;
        const float* xp0 = xpb + (size_t)xrow0 * (GATES*64);
        #pragma unroll
        for (int r = 0; r < 2; r++)
            #pragma unroll
            for (int gate = 0; gate < 4; gate++)
                xr[r][gate] = __ldcg(&xp0[((gate << 9) + kc*8 + j0 + r)*64 + pb]);
    }
    bar_wait(slots, tgt);

    for (int t = 0; t < SEQ; t++) {
        const uint32_t* hbin  = g_hb + (size_t)(((t  )&1)*2 + dir)*32*512;
        uint32_t*       hbout = g_hb + (size_t)(((t+1)&1)*2 + dir)*32*512;

        float acc[2][4][4];
        #pragma unroll
        for (int mf = 0; mf < 2; mf++)
            #pragma unroll
            for (int nt = 0; nt < 4; nt++)
                #pragma unroll
                for (int q = 0; q < 4; q++) acc[mf][nt][q] = 0.f;

        // --- MMA: h fragments straight from L2 (coalesced 256B per frag) ---
        #pragma unroll
        for (int kt = 0; kt < 8; kt++) {
            const uint32_t* base = hbin + (ks*8 + kt)*512;
            #pragma unroll
            for (int nt = 0; nt < 4; nt++) {
                uint2 bb = ldcg_u2(base + (nh*32 + nt*8 + g)*8 + 2*tq);
                mma16(acc[0][nt], aw[kt][0], bb.x, bb.y);
                mma16(acc[1][nt], aw[kt][1], bb.x, bb.y);
            }
        }

        // --- write k-partials ---
        #pragma unroll
        for (int mf = 0; mf < 2; mf++)
            #pragma unroll
            for (int nt = 0; nt < 4; nt++) {
                int b = nh*32 + nt*8 + 2*tq;
                *(float2*)&sG[(ks*32 + mf*16 + g    )*SGP + b] =
                    make_float2(acc[mf][nt][0], acc[mf][nt][1]);
                *(float2*)&sG[(ks*32 + mf*16 + g + 8)*SGP + b] =
                    make_float2(acc[mf][nt][2], acc[mf][nt][3]);
            }
        __syncthreads();

        // --- pointwise: thread owns cells (j0, pb), (j0+1, pb) ---
        float hv[2];
        #pragma unroll
        for (int r = 0; r < 2; r++) {
            int j = j0 + r;
            int kg = kc*8 + j;
            float v[4];
            #pragma unroll
            for (int gate = 0; gate < 4; gate++) {
                float s = xr[r][gate];
                #pragma unroll
                for (int k2 = 0; k2 < 4; k2++)
                    s += sG[(k2*32 + gate*8 + j)*SGP + pb];
                v[gate] = s;
            }
            float f  = sig_ap(v[0]);
            float ii = sig_ap(v[1]);
            float gg = tanh_ap(v[2]);
            float o  = sig_ap(v[3]);
            float c = f*creg[r] + ii*gg;
            creg[r] = c;
            hv[r] = o*tanh_ap(c);
            if (t == SEQ-1)
                g_h[dir*HB + pb*HID + kg] = hv[r];
        }
        // pack pair -> permuted bf16 global h (+ hs history for layer-1 GEMM)
        {
            uint32_t w = pk(hv[0], hv[1]);
            int pos = j0 + (kc & 1);
            hbout[((kc >> 1)*64 + pb)*8 + pos] = w;
            if (store_hs)
                hsb[((size_t)(t*32 + (kc >> 1))*64 + pb)*8 + pos] = w;
        }

        // --- barrier with xp(t+1) prefetch hidden in the wait slack ---
        tgt++;
        bar_arrive(slots, kc, tgt);
        if (t + 1 < SEQ) {
            int tn = t + 1;
            int xrow = (dir && rev_b) ? (SEQ-1-tn) : tn;
            const float* xpn = xpb + (size_t)xrow * (GATES*64);
            #pragma unroll
            for (int r = 0; r < 2; r++)
                #pragma unroll
                for (int gate = 0; gate < 4; gate++)
                    xr[r][gate] = __ldcg(&xpn[((gate << 9) + kc*8 + j0 + r)*64 + pb]);
        }
        bar_wait(slots, tgt);
    }
}

// ---------------------------------------------------------------------------
// Final FC + sigmoid. Final fp32 states in g_h[dir][b][k].
// ---------------------------------------------------------------------------
__global__ void final_fc(const float* __restrict__ fcw, const float* __restrict__ fcb,
                         float* __restrict__ out)
{
    int b = blockIdx.x;
    const float* hf = g_h + b*HID;
    const float* hb = g_h + HB + b*HID;
    float s = 0.f;
    for (int k = threadIdx.x; k < HID; k += 128)
        s += hf[k]*fcw[k] + hb[k]*fcw[HID + k];
    #pragma unroll
    for (int off = 16; off > 0; off >>= 1)
        s += __shfl_xor_sync(0xFFFFFFFFu, s, off);
    __shared__ float red[4];
    int warp = threadIdx.x >> 5, lane = threadIdx.x & 31;
    if (lane == 0) red[warp] = s;
    __syncthreads();
    if (threadIdx.x == 0) {
        float tot = red[0] + red[1] + red[2] + red[3] + fcb[0];
        out[b] = 1.f/(1.f + expf(-tot));
    }
}

// ---------------------------------------------------------------------------
// Launch sequence: 7 graph nodes.
// ---------------------------------------------------------------------------
extern "C" void kernel_launch(void* const* d_in, const int* in_sizes, int n_in,
                              void* d_out, int out_size)
{
    const int*   x    = (const int*)  d_in[0];
    const float* emb  = (const float*)d_in[1];
    const float* Wx_f = (const float*)d_in[2];
    const float* bx_f = (const float*)d_in[3];
    const float* Wh_f = (const float*)d_in[4];
    const float* bh_f = (const float*)d_in[5];
    const float* Wx_b = (const float*)d_in[6];
    const float* bx_b = (const float*)d_in[7];
    const float* Wh_b = (const float*)d_in[8];
    const float* bh_b = (const float*)d_in[9];
    const float* fcw  = (const float*)d_in[10];
    const float* fcb  = (const float*)d_in[11];
    float* out = (float*)d_out;

    const int WL = 4*HID*HID;
    const int BL = 4*HID;

    dim3 ggrid(GATES/128, MROWS/128, 2);   // (16, 256, 2)

    // 1. pre-pack Wx tensors to bf16 permuted global ([l*2+d] order)
    pack_w<<<dim3(GATES/8, 4), 256>>>(Wx_f, Wx_b, Wx_f + WL, Wx_b + WL);

    // 2. embedding -> packed bf16 xe
    embed_kernel<<<MROWS/8, 256>>>(x, emb);

    // 3. layer-0 input projections (A = xe), bias = bx + bh
    gemm_xproj<<<ggrid, 256>>>(0, 0, bx_f, bh_f, bx_b, bh_b);

    // 4. layer-0 recurrence (backward reads xp row 511-t, store hs)
    lstm_layer<<<NBLK, 256>>>(Wh_f, Wh_b, 1, 1);

    // 5. layer-1 input projections (A = packed bf16 hs per dir)
    gemm_xproj<<<ggrid, 256>>>(1, 1, bx_f + BL, bh_f + BL, bx_b + BL, bh_b + BL);

    // 6. layer-1 recurrence (both dirs read xp row t)
    lstm_layer<<<NBLK, 256>>>(Wh_f + WL, Wh_b + WL, 0, 0);

    // 7. final FC + sigmoid
    final_fc<<<BATCH, 128>>>(fcw, fcb, out);
}